// round 12
// baseline (speedup 1.0000x reference)
#include <cuda_runtime.h>
#include <cuda_bf16.h>
#include <cstdint>

// SkeletonLinear: out = x @ (W .* M)^T + b
// x: [32768, 768] f32, W: [768, 768] f32, b: [768], out: [32768, 768] f32.
// Mask structure (fixed): node d's 64-col window [32(d-1), 32(d-1)+64) is all
// ones for d>0; for d==0 the window is cols [0,64) with the upper 32 cols
// zero. The mask tensor is never read.
//
// R11: cp.async double-buffered multi-tile pipeline. CTA = 256 thr / node d /
// 4 tiles x 64 rows. x copied raw fp32 gmem->smem with cp.async (tile t+1
// overlaps compute of tile t); w split-staged to bf16 hi/lo ONCE per CTA.
// A fragments: LDS.64 raw fp32 + in-register truncation split (hi = top16
// via PRMT, lo = exact residual -> bf16x2). 3 accumulating mma.m16n8k16
// (hh + hl + lh). Warp tile = 16 rows x 16 outputs, bias folded into acc.

#define NODES   24
#define CH      32
#define DIM     768
#define BATCH   32768
#define TROWS   64    // rows per pipeline tile
#define TILES   4     // tiles per CTA
#define THREADS 256
#define XS      68    // float stride per raw x row (64 + 4 pad; == 4 mod 32)
#define PAD     36    // uint32 word stride per w row (32 data + 4 pad)

__device__ __forceinline__ uint32_t smem_u32(const void* p) {
    return (uint32_t)__cvta_generic_to_shared(p);
}
__device__ __forceinline__ void cp16(uint32_t dst, const void* src) {
    asm volatile("cp.async.cg.shared.global [%0], [%1], 16;"
                 :: "r"(dst), "l"(src));
}
__device__ __forceinline__ void cp_commit() {
    asm volatile("cp.async.commit_group;");
}
template <int N>
__device__ __forceinline__ void cp_wait() {
    asm volatile("cp.async.wait_group %0;" :: "n"(N));
}

__device__ __forceinline__ void mma_bf16(float c[4],
                                         uint32_t a0, uint32_t a1,
                                         uint32_t a2, uint32_t a3,
                                         uint32_t b0, uint32_t b1) {
    asm volatile(
        "mma.sync.aligned.m16n8k16.row.col.f32.bf16.bf16.f32 "
        "{%0,%1,%2,%3}, {%4,%5,%6,%7}, {%8,%9}, {%0,%1,%2,%3};"
        : "+f"(c[0]), "+f"(c[1]), "+f"(c[2]), "+f"(c[3])
        : "r"(a0), "r"(a1), "r"(a2), "r"(a3), "r"(b0), "r"(b1));
}

// truncation split of a float2: hi = top-16-bits bf16x2 (1 PRMT), lo = exact
// residual rounded to bf16x2. Dropped ll term ~2^-16 rel -> rel_err ~1e-5.
__device__ __forceinline__ void split_trunc(uint2 u, uint32_t& hi, uint32_t& lo) {
    hi = __byte_perm(u.x, u.y, 0x7632);
    float lx = __uint_as_float(u.x) - __uint_as_float(u.x & 0xFFFF0000u);
    float ly = __uint_as_float(u.y) - __uint_as_float(u.y & 0xFFFF0000u);
    __nv_bfloat162 l = __floats2bfloat162_rn(lx, ly);
    lo = *reinterpret_cast<uint32_t*>(&l);
}

__global__ void __launch_bounds__(THREADS, 4)
skeleton_linear_kernel(const float* __restrict__ x,
                       const float* __restrict__ w,
                       const float* __restrict__ bias,
                       float* __restrict__ out) {
    const int d    = blockIdx.y;
    const int rowg = blockIdx.x * (TROWS * TILES);   // 256-row strip
    const int tid  = threadIdx.x;
    const int col0 = (d == 0) ? 0 : (d - 1) * CH;

    __shared__ float    xraw[2][TROWS * XS];   // raw fp32 x tiles (double buf)
    __shared__ uint32_t ws_hi[CH * PAD];       // bf16x2 split weights
    __shared__ uint32_t ws_lo[CH * PAD];
    __shared__ float    bs[CH];

    // ---- cp.async prefetch of one 64-row x tile (raw fp32, 16B chunks) ----
    auto prefetch = [&](int t, int b) {
        const float* src0 = x + (rowg + t * TROWS) * DIM + col0;
        uint32_t dst0 = smem_u32(&xraw[b][0]);
        #pragma unroll
        for (int it = 0; it < (TROWS * 16) / THREADS; ++it) {  // 4 iters
            int idx = tid + it * THREADS;      // 0..1023
            int r   = idx >> 4;                // row 0..63
            int c4  = idx & 15;                // float4 chunk
            cp16(dst0 + (uint32_t)(r * XS + c4 * 4) * 4u,
                 src0 + r * DIM + c4 * 4);
        }
    };

    prefetch(0, 0);
    cp_commit();

    // ---- stage weights once (masked, split bf16 hi/lo), in copy shadow ----
    {
        const int wbase = d * CH * DIM + col0;
        #pragma unroll
        for (int it = 0; it < (CH * 32) / THREADS; ++it) {     // 4 iters
            int idx = tid + it * THREADS;
            int o   = idx >> 5;
            int c2  = idx & 31;
            uint2 u = *reinterpret_cast<const uint2*>(w + wbase + o * DIM + c2 * 2);
            if (d == 0 && c2 >= 16) { u.x = 0u; u.y = 0u; }
            uint32_t h, l;
            split_trunc(u, h, l);
            ws_hi[o * PAD + c2] = h;
            ws_lo[o * PAD + c2] = l;
        }
        if (tid < CH) bs[tid] = bias[d * CH + tid];
    }

    const int lane = tid & 31;
    const int warp = tid >> 5;              // 0..7
    const int grp  = lane >> 2;             // 0..7
    const int tig  = lane & 3;              // 0..3
    const int r0w  = (warp & 3) * 16;       // warp row base within tile
    const int og   = (warp >> 2) * 16;      // warp output base (16 outputs)

    #pragma unroll 1
    for (int t = 0; t < TILES; ++t) {
        if (t + 1 < TILES) { prefetch(t + 1, (t + 1) & 1); cp_commit(); }
        if (t + 1 < TILES) cp_wait<1>(); else cp_wait<0>();
        __syncthreads();

        const float* xb = &xraw[t & 1][0] + (r0w + grp) * XS + 2 * tig;

        // bias folded into accumulator init
        float acc[2][4];
        #pragma unroll
        for (int n = 0; n < 2; ++n) {
            float b0 = bs[og + n * 8 + tig * 2];
            float b1 = bs[og + n * 8 + tig * 2 + 1];
            acc[n][0] = b0; acc[n][1] = b1; acc[n][2] = b0; acc[n][3] = b1;
        }

        #pragma unroll
        for (int kk = 0; kk < 4; ++kk) {    // K = 64 -> 4 k16-steps
            const float* p = xb + kk * 16;
            uint2 u00 = *reinterpret_cast<const uint2*>(p);            // row, klow
            uint2 u10 = *reinterpret_cast<const uint2*>(p + 8 * XS);   // row+8
            uint2 u01 = *reinterpret_cast<const uint2*>(p + 8);        // row, khigh
            uint2 u11 = *reinterpret_cast<const uint2*>(p + 8 * XS + 8);
            uint32_t a0h, a0l, a1h, a1l, a2h, a2l, a3h, a3l;
            split_trunc(u00, a0h, a0l);
            split_trunc(u10, a1h, a1l);
            split_trunc(u01, a2h, a2l);
            split_trunc(u11, a3h, a3l);
            const int kw = kk * 8;
            #pragma unroll
            for (int n = 0; n < 2; ++n) {
                int wrow = (og + n * 8 + grp) * PAD + tig;
                uint32_t bh0 = ws_hi[wrow + kw], bh1 = ws_hi[wrow + kw + 4];
                uint32_t bl0 = ws_lo[wrow + kw], bl1 = ws_lo[wrow + kw + 4];
                mma_bf16(acc[n], a0h, a1h, a2h, a3h, bh0, bh1); // hh
                mma_bf16(acc[n], a0h, a1h, a2h, a3h, bl0, bl1); // hl
                mma_bf16(acc[n], a0l, a1l, a2l, a3l, bh0, bh1); // lh
            }
        }

        // ---- epilogue: float2 stores (bias already in acc) ----
        const int p0 = (rowg + t * TROWS + r0w + grp) * DIM + d * CH
                       + og + tig * 2;
        #pragma unroll
        for (int n = 0; n < 2; ++n) {
            *reinterpret_cast<float2*>(out + p0 + n * 8) =
                make_float2(acc[n][0], acc[n][1]);
            *reinterpret_cast<float2*>(out + p0 + 8 * DIM + n * 8) =
                make_float2(acc[n][2], acc[n][3]);
        }

        __syncthreads();   // all reads of this buffer done before re-fill
    }
}

extern "C" void kernel_launch(void* const* d_in, const int* in_sizes, int n_in,
                              void* d_out, int out_size) {
    const float* x    = (const float*)d_in[0];
    const float* w    = (const float*)d_in[1];
    const float* b    = (const float*)d_in[2];
    // d_in[3] (mask) is structurally known; not read.
    float* out = (float*)d_out;

    dim3 grid(BATCH / (TROWS * TILES), NODES);  // (128, 24)
    skeleton_linear_kernel<<<grid, THREADS>>>(x, w, b, out);
}

// round 14
// speedup vs baseline: 1.1355x; 1.1355x over previous
#include <cuda_runtime.h>
#include <cuda_bf16.h>
#include <cstdint>

// SkeletonLinear: out = x @ (W .* M)^T + b
// x: [32768, 768] f32, W: [768, 768] f32, b: [768], out: [32768, 768] f32.
// Mask structure (fixed): node d's 64-col window [32(d-1), 32(d-1)+64) is all
// ones for d>0; for d==0 the window is cols [0,64) with the upper 32 cols
// zero. The mask tensor is never read.
//
// R13 = R11 + B fragments hoisted into registers (loop-invariant across row
// tiles; kills the dominant redundant smem traffic) + TILES 4->8 (512-row
// strips amortize w staging / B load twice as far). CTA = 256 thr / node d /
// 8 tiles x 64 rows, cp.async double-buffered x pipeline (raw fp32), A
// fragments split in-register (truncation hi/lo bf16), 3 accumulating
// mma.m16n8k16 (hh + hl + lh). Warp tile = 16 rows x 16 outputs.

#define NODES   24
#define CH      32
#define DIM     768
#define BATCH   32768
#define TROWS   64    // rows per pipeline tile
#define TILES   8     // tiles per CTA
#define THREADS 256
#define XS      68    // float stride per raw x row (64 + 4 pad; == 4 mod 32)
#define PAD     36    // uint32 word stride per w row (32 data + 4 pad)

__device__ __forceinline__ uint32_t smem_u32(const void* p) {
    return (uint32_t)__cvta_generic_to_shared(p);
}
__device__ __forceinline__ void cp16(uint32_t dst, const void* src) {
    asm volatile("cp.async.cg.shared.global [%0], [%1], 16;"
                 :: "r"(dst), "l"(src));
}
__device__ __forceinline__ void cp_commit() {
    asm volatile("cp.async.commit_group;");
}
template <int N>
__device__ __forceinline__ void cp_wait() {
    asm volatile("cp.async.wait_group %0;" :: "n"(N));
}

__device__ __forceinline__ void mma_bf16(float c[4],
                                         uint32_t a0, uint32_t a1,
                                         uint32_t a2, uint32_t a3,
                                         uint32_t b0, uint32_t b1) {
    asm volatile(
        "mma.sync.aligned.m16n8k16.row.col.f32.bf16.bf16.f32 "
        "{%0,%1,%2,%3}, {%4,%5,%6,%7}, {%8,%9}, {%0,%1,%2,%3};"
        : "+f"(c[0]), "+f"(c[1]), "+f"(c[2]), "+f"(c[3])
        : "r"(a0), "r"(a1), "r"(a2), "r"(a3), "r"(b0), "r"(b1));
}

// truncation split of a float2: hi = top-16-bits bf16x2 (1 PRMT), lo = exact
// residual rounded to bf16x2. Dropped ll term ~2^-16 rel -> rel_err ~1e-5.
__device__ __forceinline__ void split_trunc(uint2 u, uint32_t& hi, uint32_t& lo) {
    hi = __byte_perm(u.x, u.y, 0x7632);
    float lx = __uint_as_float(u.x) - __uint_as_float(u.x & 0xFFFF0000u);
    float ly = __uint_as_float(u.y) - __uint_as_float(u.y & 0xFFFF0000u);
    __nv_bfloat162 l = __floats2bfloat162_rn(lx, ly);
    lo = *reinterpret_cast<uint32_t*>(&l);
}

__global__ void __launch_bounds__(THREADS)
skeleton_linear_kernel(const float* __restrict__ x,
                       const float* __restrict__ w,
                       const float* __restrict__ bias,
                       float* __restrict__ out) {
    const int d    = blockIdx.y;
    const int rowg = blockIdx.x * (TROWS * TILES);   // 512-row strip
    const int tid  = threadIdx.x;
    const int col0 = (d == 0) ? 0 : (d - 1) * CH;

    __shared__ float    xraw[2][TROWS * XS];   // raw fp32 x tiles (double buf)
    __shared__ uint32_t ws_hi[CH * PAD];       // bf16x2 split weights
    __shared__ uint32_t ws_lo[CH * PAD];
    __shared__ float    bs[CH];

    // ---- cp.async prefetch of one 64-row x tile (raw fp32, 16B chunks) ----
    auto prefetch = [&](int t, int b) {
        const float* src0 = x + (rowg + t * TROWS) * DIM + col0;
        uint32_t dst0 = smem_u32(&xraw[b][0]);
        #pragma unroll
        for (int it = 0; it < (TROWS * 16) / THREADS; ++it) {  // 4 iters
            int idx = tid + it * THREADS;      // 0..1023
            int r   = idx >> 4;                // row 0..63
            int c4  = idx & 15;                // float4 chunk
            cp16(dst0 + (uint32_t)(r * XS + c4 * 4) * 4u,
                 src0 + r * DIM + c4 * 4);
        }
    };

    prefetch(0, 0);
    cp_commit();

    // ---- stage weights once (masked, split bf16 hi/lo), in copy shadow ----
    {
        const int wbase = d * CH * DIM + col0;
        #pragma unroll
        for (int it = 0; it < (CH * 32) / THREADS; ++it) {     // 4 iters
            int idx = tid + it * THREADS;
            int o   = idx >> 5;
            int c2  = idx & 31;
            uint2 u = *reinterpret_cast<const uint2*>(w + wbase + o * DIM + c2 * 2);
            if (d == 0 && c2 >= 16) { u.x = 0u; u.y = 0u; }
            uint32_t h, l;
            split_trunc(u, h, l);
            ws_hi[o * PAD + c2] = h;
            ws_lo[o * PAD + c2] = l;
        }
        if (tid < CH) bs[tid] = bias[d * CH + tid];
    }
    __syncthreads();   // w staged before B-fragment hoist

    const int lane = tid & 31;
    const int warp = tid >> 5;              // 0..7
    const int grp  = lane >> 2;             // 0..7
    const int tig  = lane & 3;              // 0..3
    const int r0w  = (warp & 3) * 16;       // warp row base within tile
    const int og   = (warp >> 2) * 16;      // warp output base (16 outputs)

    // ---- hoist B fragments to registers (loop-invariant across tiles) ----
    uint32_t Bh[2][4][2], Bl[2][4][2];      // [n][kk][word]
    #pragma unroll
    for (int kk = 0; kk < 4; ++kk) {
        const int kw = kk * 8;
        #pragma unroll
        for (int n = 0; n < 2; ++n) {
            int wrow = (og + n * 8 + grp) * PAD + tig;
            Bh[n][kk][0] = ws_hi[wrow + kw];
            Bh[n][kk][1] = ws_hi[wrow + kw + 4];
            Bl[n][kk][0] = ws_lo[wrow + kw];
            Bl[n][kk][1] = ws_lo[wrow + kw + 4];
        }
    }
    // bias values for accumulator init
    const float bv0 = bs[og + tig * 2],      bv1 = bs[og + tig * 2 + 1];
    const float bv2 = bs[og + 8 + tig * 2],  bv3 = bs[og + 8 + tig * 2 + 1];

    #pragma unroll 1
    for (int t = 0; t < TILES; ++t) {
        if (t + 1 < TILES) { prefetch(t + 1, (t + 1) & 1); cp_commit(); }
        if (t + 1 < TILES) cp_wait<1>(); else cp_wait<0>();
        __syncthreads();

        const float* xb = &xraw[t & 1][0] + (r0w + grp) * XS + 2 * tig;

        float acc[2][4];
        acc[0][0] = bv0; acc[0][1] = bv1; acc[0][2] = bv0; acc[0][3] = bv1;
        acc[1][0] = bv2; acc[1][1] = bv3; acc[1][2] = bv2; acc[1][3] = bv3;

        #pragma unroll
        for (int kk = 0; kk < 4; ++kk) {    // K = 64 -> 4 k16-steps
            const float* p = xb + kk * 16;
            uint2 u00 = *reinterpret_cast<const uint2*>(p);            // row, klow
            uint2 u10 = *reinterpret_cast<const uint2*>(p + 8 * XS);   // row+8
            uint2 u01 = *reinterpret_cast<const uint2*>(p + 8);        // row, khigh
            uint2 u11 = *reinterpret_cast<const uint2*>(p + 8 * XS + 8);
            uint32_t a0h, a0l, a1h, a1l, a2h, a2l, a3h, a3l;
            split_trunc(u00, a0h, a0l);
            split_trunc(u10, a1h, a1l);
            split_trunc(u01, a2h, a2l);
            split_trunc(u11, a3h, a3l);
            #pragma unroll
            for (int n = 0; n < 2; ++n) {
                mma_bf16(acc[n], a0h, a1h, a2h, a3h,
                         Bh[n][kk][0], Bh[n][kk][1]);               // hh
                mma_bf16(acc[n], a0h, a1h, a2h, a3h,
                         Bl[n][kk][0], Bl[n][kk][1]);               // hl
                mma_bf16(acc[n], a0l, a1l, a2l, a3l,
                         Bh[n][kk][0], Bh[n][kk][1]);               // lh
            }
        }

        // ---- epilogue: float2 stores (bias already in acc) ----
        const int p0 = (rowg + t * TROWS + r0w + grp) * DIM + d * CH
                       + og + tig * 2;
        #pragma unroll
        for (int n = 0; n < 2; ++n) {
            *reinterpret_cast<float2*>(out + p0 + n * 8) =
                make_float2(acc[n][0], acc[n][1]);
            *reinterpret_cast<float2*>(out + p0 + 8 * DIM + n * 8) =
                make_float2(acc[n][2], acc[n][3]);
        }

        __syncthreads();   // all reads of this buffer done before re-fill
    }
}

extern "C" void kernel_launch(void* const* d_in, const int* in_sizes, int n_in,
                              void* d_out, int out_size) {
    const float* x    = (const float*)d_in[0];
    const float* w    = (const float*)d_in[1];
    const float* b    = (const float*)d_in[2];
    // d_in[3] (mask) is structurally known; not read.
    float* out = (float*)d_out;

    dim3 grid(BATCH / (TROWS * TILES), NODES);  // (64, 24)
    skeleton_linear_kernel<<<grid, THREADS>>>(x, w, b, out);
}

// round 16
// speedup vs baseline: 1.2705x; 1.1189x over previous
#include <cuda_runtime.h>
#include <cuda_bf16.h>
#include <cstdint>

// SkeletonLinear: out = x @ (W .* M)^T + b
// x: [32768, 768] f32, W: [768, 768] f32, b: [768], out: [32768, 768] f32.
// Mask structure (fixed): node d's 64-col window [32(d-1), 32(d-1)+64) is all
// ones for d>0; for d==0 the window is cols [0,64) with the upper 32 cols
// zero. The mask tensor is never read.
//
// R15 = R13 with warp tile widened to 16 rows x 32 outputs (all 4 n-groups):
// each x element is split to bf16 hi/lo ONCE per CTA and feeds 12 MMAs
// (split:mma ratio halved). CTA = 128 thr (4 warps) / node d / 8 tiles x
// 64 rows, cp.async double-buffered raw-fp32 x pipeline, B fragments fully
// hoisted to registers (Bh+Bl), bias folded into accumulator init.

#define NODES   24
#define CH      32
#define DIM     768
#define BATCH   32768
#define TROWS   64    // rows per pipeline tile
#define TILES   8     // tiles per CTA
#define THREADS 128
#define XS      68    // float stride per raw x row (64 + 4 pad)
#define PAD     36    // uint32 word stride per w row (32 data + 4 pad)

__device__ __forceinline__ uint32_t smem_u32(const void* p) {
    return (uint32_t)__cvta_generic_to_shared(p);
}
__device__ __forceinline__ void cp16(uint32_t dst, const void* src) {
    asm volatile("cp.async.cg.shared.global [%0], [%1], 16;"
                 :: "r"(dst), "l"(src));
}
__device__ __forceinline__ void cp_commit() {
    asm volatile("cp.async.commit_group;");
}
template <int N>
__device__ __forceinline__ void cp_wait() {
    asm volatile("cp.async.wait_group %0;" :: "n"(N));
}

__device__ __forceinline__ void mma_bf16(float c[4],
                                         uint32_t a0, uint32_t a1,
                                         uint32_t a2, uint32_t a3,
                                         uint32_t b0, uint32_t b1) {
    asm volatile(
        "mma.sync.aligned.m16n8k16.row.col.f32.bf16.bf16.f32 "
        "{%0,%1,%2,%3}, {%4,%5,%6,%7}, {%8,%9}, {%0,%1,%2,%3};"
        : "+f"(c[0]), "+f"(c[1]), "+f"(c[2]), "+f"(c[3])
        : "r"(a0), "r"(a1), "r"(a2), "r"(a3), "r"(b0), "r"(b1));
}

// truncation split of a float2: hi = top-16-bits bf16x2 (1 PRMT), lo = exact
// residual rounded to bf16x2. Dropped ll term ~2^-16 rel -> rel_err ~1e-5.
__device__ __forceinline__ void split_trunc(uint2 u, uint32_t& hi, uint32_t& lo) {
    hi = __byte_perm(u.x, u.y, 0x7632);
    float lx = __uint_as_float(u.x) - __uint_as_float(u.x & 0xFFFF0000u);
    float ly = __uint_as_float(u.y) - __uint_as_float(u.y & 0xFFFF0000u);
    __nv_bfloat162 l = __floats2bfloat162_rn(lx, ly);
    lo = *reinterpret_cast<uint32_t*>(&l);
}

__global__ void __launch_bounds__(THREADS, 4)
skeleton_linear_kernel(const float* __restrict__ x,
                       const float* __restrict__ w,
                       const float* __restrict__ bias,
                       float* __restrict__ out) {
    const int d    = blockIdx.y;
    const int rowg = blockIdx.x * (TROWS * TILES);   // 512-row strip
    const int tid  = threadIdx.x;
    const int col0 = (d == 0) ? 0 : (d - 1) * CH;

    __shared__ float    xraw[2][TROWS * XS];   // raw fp32 x tiles (double buf)
    __shared__ uint32_t ws_hi[CH * PAD];       // bf16x2 split weights
    __shared__ uint32_t ws_lo[CH * PAD];
    __shared__ float    bs[CH];

    // ---- cp.async prefetch of one 64-row x tile (raw fp32, 16B chunks) ----
    auto prefetch = [&](int t, int b) {
        const float* src0 = x + (rowg + t * TROWS) * DIM + col0;
        uint32_t dst0 = smem_u32(&xraw[b][0]);
        #pragma unroll
        for (int it = 0; it < (TROWS * 16) / THREADS; ++it) {  // 8 iters
            int idx = tid + it * THREADS;      // 0..1023
            int r   = idx >> 4;                // row 0..63
            int c4  = idx & 15;                // float4 chunk
            cp16(dst0 + (uint32_t)(r * XS + c4 * 4) * 4u,
                 src0 + r * DIM + c4 * 4);
        }
    };

    prefetch(0, 0);
    cp_commit();

    // ---- stage weights once (masked, split bf16 hi/lo), in copy shadow ----
    {
        const int wbase = d * CH * DIM + col0;
        #pragma unroll
        for (int it = 0; it < (CH * 32) / THREADS; ++it) {     // 8 iters
            int idx = tid + it * THREADS;
            int o   = idx >> 5;
            int c2  = idx & 31;
            uint2 u = *reinterpret_cast<const uint2*>(w + wbase + o * DIM + c2 * 2);
            if (d == 0 && c2 >= 16) { u.x = 0u; u.y = 0u; }
            uint32_t h, l;
            split_trunc(u, h, l);
            ws_hi[o * PAD + c2] = h;
            ws_lo[o * PAD + c2] = l;
        }
        if (tid < CH) bs[tid] = bias[d * CH + tid];
    }
    __syncthreads();   // w staged before B-fragment hoist

    const int lane = tid & 31;
    const int warp = tid >> 5;              // 0..3 -> row group
    const int grp  = lane >> 2;             // 0..7
    const int tig  = lane & 3;              // 0..3
    const int r0w  = warp * 16;             // warp row base within tile

    // ---- hoist ALL B fragments to registers (4 n-groups x 4 kk x hi/lo) ----
    uint32_t Bh[4][4][2], Bl[4][4][2];      // [n][kk][word]
    #pragma unroll
    for (int kk = 0; kk < 4; ++kk) {
        const int kw = kk * 8;
        #pragma unroll
        for (int n = 0; n < 4; ++n) {
            int wrow = (n * 8 + grp) * PAD + tig;
            Bh[n][kk][0] = ws_hi[wrow + kw];
            Bh[n][kk][1] = ws_hi[wrow + kw + 4];
            Bl[n][kk][0] = ws_lo[wrow + kw];
            Bl[n][kk][1] = ws_lo[wrow + kw + 4];
        }
    }
    // bias values for accumulator init (per n-group, cols tig*2, tig*2+1)
    float bv[4][2];
    #pragma unroll
    for (int n = 0; n < 4; ++n) {
        bv[n][0] = bs[n * 8 + tig * 2];
        bv[n][1] = bs[n * 8 + tig * 2 + 1];
    }

    #pragma unroll 1
    for (int t = 0; t < TILES; ++t) {
        if (t + 1 < TILES) { prefetch(t + 1, (t + 1) & 1); cp_commit(); }
        if (t + 1 < TILES) cp_wait<1>(); else cp_wait<0>();
        __syncthreads();

        const float* xb = &xraw[t & 1][0] + (r0w + grp) * XS + 2 * tig;

        float acc[4][4];
        #pragma unroll
        for (int n = 0; n < 4; ++n) {
            acc[n][0] = bv[n][0]; acc[n][1] = bv[n][1];
            acc[n][2] = bv[n][0]; acc[n][3] = bv[n][1];
        }

        #pragma unroll
        for (int kk = 0; kk < 4; ++kk) {    // K = 64 -> 4 k16-steps
            const float* p = xb + kk * 16;
            uint2 u00 = *reinterpret_cast<const uint2*>(p);            // row, klow
            uint2 u10 = *reinterpret_cast<const uint2*>(p + 8 * XS);   // row+8
            uint2 u01 = *reinterpret_cast<const uint2*>(p + 8);        // row, khigh
            uint2 u11 = *reinterpret_cast<const uint2*>(p + 8 * XS + 8);
            uint32_t a0h, a0l, a1h, a1l, a2h, a2l, a3h, a3l;
            split_trunc(u00, a0h, a0l);
            split_trunc(u10, a1h, a1l);
            split_trunc(u01, a2h, a2l);
            split_trunc(u11, a3h, a3l);
            #pragma unroll
            for (int n = 0; n < 4; ++n) {
                mma_bf16(acc[n], a0h, a1h, a2h, a3h,
                         Bh[n][kk][0], Bh[n][kk][1]);               // hh
                mma_bf16(acc[n], a0h, a1h, a2h, a3h,
                         Bl[n][kk][0], Bl[n][kk][1]);               // hl
                mma_bf16(acc[n], a0l, a1l, a2l, a3l,
                         Bh[n][kk][0], Bh[n][kk][1]);               // lh
            }
        }

        // ---- epilogue: float2 stores (bias already in acc) ----
        const int p0 = (rowg + t * TROWS + r0w + grp) * DIM + d * CH + tig * 2;
        #pragma unroll
        for (int n = 0; n < 4; ++n) {
            *reinterpret_cast<float2*>(out + p0 + n * 8) =
                make_float2(acc[n][0], acc[n][1]);
            *reinterpret_cast<float2*>(out + p0 + 8 * DIM + n * 8) =
                make_float2(acc[n][2], acc[n][3]);
        }

        __syncthreads();   // all reads of this buffer done before re-fill
    }
}

extern "C" void kernel_launch(void* const* d_in, const int* in_sizes, int n_in,
                              void* d_out, int out_size) {
    const float* x    = (const float*)d_in[0];
    const float* w    = (const float*)d_in[1];
    const float* b    = (const float*)d_in[2];
    // d_in[3] (mask) is structurally known; not read.
    float* out = (float*)d_out;

    dim3 grid(BATCH / (TROWS * TILES), NODES);  // (64, 24)
    skeleton_linear_kernel<<<grid, THREADS>>>(x, w, b, out);
}